// round 16
// baseline (speedup 1.0000x reference)
#include <cuda_runtime.h>
#include <cstdint>

#if defined(__CUDA_ARCH__) && (defined(__CUDA_ARCH_FEAT_SM103_ALL) || defined(__CUDA_ARCH_FEAT_SM100_ALL) || defined(__CUDA_ARCH_SPECIFIC__))
#define HAS_TC 1
#else
#define HAS_TC 0
#endif

#define NOISE   128
#define OUTF    512
#define XCOLS   640
#define WCOLS   262656
#define WB_OFF  262144

// chunk space: 2048 main (i0-outer, k-inner) + 16 feat-bias + 4 noise-bias + 1 const
#define CHUNKS  2069
#define SPLITS  74
#define CHPER   28
#define NST     3
#define NTHREADS 544       // warp 0 = MMA warp, warps 1-16 = 512 stagers
#define NCTAS   (2 * SPLITS)               // 148 (1 CTA per SM)
#define NT_TOTAL (NCTAS * NTHREADS)
#define ELEMS2  65536

#define SM_A(st, mt) (1024u + ((st)*2u + (mt))*16384u)    // 6 x 16KB A tiles
#define SM_B(st)     (99328u + (st)*32768u)               // 3 x 32KB B tiles
#define SMEM_TOTAL   197632
#define SM_FULL(st)  (8u  + (st)*8u)
#define SM_EMPTY(st) (40u + (st)*8u)

// idesc: dtype F32(1)@[4], a/b TF32(2)@[7:9]/[10:12], N=256 -> 32@[17:22], M=128 -> 8@[24:28]
#define IDESC_TF32 ((1u<<4)|(2u<<7)|(2u<<10)|(32u<<17)|(8u<<24))

__device__ float g_scratch[(size_t)SPLITS * 256 * 512];   // split partials (38.8MB)
__device__ unsigned g_bar_cnt = 0;
__device__ volatile unsigned g_bar_sense = 0;

#if HAS_TC
__device__ __forceinline__ uint32_t smem_u32(const void* p){
    uint32_t a;
    asm("{ .reg .u64 t; cvta.to.shared.u64 t, %1; cvt.u32.u64 %0, t; }" : "=r"(a) : "l"(p));
    return a;
}
__device__ __forceinline__ uint32_t sw128(uint32_t o){ return o ^ ((o >> 3) & 0x70u); }
__device__ __forceinline__ uint32_t f2tf32(float f){
    uint32_t r; asm("cvt.rna.tf32.f32 %0, %1;" : "=r"(r) : "f"(f)); return r;
}
__device__ __forceinline__ void sts128(uint32_t addr, uint32_t a, uint32_t b, uint32_t c, uint32_t d){
    asm volatile("st.shared.v4.b32 [%0], {%1,%2,%3,%4};"
                 :: "r"(addr), "r"(a), "r"(b), "r"(c), "r"(d) : "memory");
}
__device__ __forceinline__ bool elect1(){
    uint32_t p;
    asm volatile("{\n\t.reg .pred P;\n\telect.sync _|P, 0xFFFFFFFF;\n\tselp.b32 %0, 1, 0, P;\n\t}" : "=r"(p));
    return p != 0;
}
static constexpr unsigned long long DESC_BASE_SW128 =
    (2ull << 61) | (1ull << 46) | (64ull << 32) | (1ull << 16);
__device__ __forceinline__ uint64_t mkdesc(uint32_t addr){
    return DESC_BASE_SW128 | (uint64_t)((addr >> 4) & 0x3FFFu);
}
__device__ __forceinline__ void mma_tf32(uint32_t d, uint64_t ad, uint64_t bd, uint32_t en){
    asm volatile(
        "{\n\t.reg .pred p;\n\tsetp.ne.u32 p, %4, 0;\n\t"
        "tcgen05.mma.cta_group::1.kind::tf32 [%0], %1, %2, %3, {%5,%5,%5,%5}, p;\n\t}"
        :: "r"(d), "l"(ad), "l"(bd), "r"(IDESC_TF32), "r"(en), "r"(0u) : "memory");
}
#define TMEM_ALLOC(smem_addr, ncols) \
    asm volatile("tcgen05.alloc.cta_group::1.sync.aligned.shared::cta.b32 [%0], %1;" \
                 :: "r"(smem_addr), "r"((uint32_t)(ncols)) : "memory")
#define TMEM_DEALLOC(tmem, ncols) \
    asm volatile("tcgen05.dealloc.cta_group::1.sync.aligned.b32 %0, %1;" :: "r"(tmem), "r"((uint32_t)(ncols)))
#define TMEM_RELINQ() asm volatile("tcgen05.relinquish_alloc_permit.cta_group::1.sync.aligned;")
#define MBAR_INIT(a, n) \
    asm volatile("mbarrier.init.shared.b64 [%0], %1;" :: "r"(a), "r"((uint32_t)(n)) : "memory")
#define MBAR_ARRIVE(a) \
    asm volatile("mbarrier.arrive.shared.b64 _, [%0];" :: "r"(a) : "memory")
#define TC_COMMIT(a) \
    asm volatile("tcgen05.commit.cta_group::1.mbarrier::arrive::one.shared::cluster.b64 [%0];" :: "r"(a) : "memory")
#define TC_FENCE_BEFORE() asm volatile("tcgen05.fence::before_thread_sync;" ::: "memory")
#define TC_FENCE_AFTER()  asm volatile("tcgen05.fence::after_thread_sync;" ::: "memory")
#define TC_WAIT_LD() asm volatile("tcgen05.wait::ld.sync.aligned;" ::: "memory")

__device__ __forceinline__ void mbar_wait(uint32_t mbar, uint32_t parity){
    uint32_t done;
    asm volatile(
        "{\n\t.reg .pred p;\n\t"
        "mbarrier.try_wait.parity.acquire.cta.shared::cta.b64 p, [%1], %2;\n\t"
        "selp.b32 %0, 1, 0, p;\n\t}"
        : "=r"(done) : "r"(mbar), "r"(parity) : "memory");
    if (!done) {
        asm volatile(
            "{\n\t.reg .pred P1;\n\t"
            "WL_%=:\n\t"
            "mbarrier.try_wait.parity.acquire.cta.shared::cta.b64 P1, [%0], %1, 0x989680;\n\t"
            "@P1 bra.uni WD_%=;\n\t"
            "bra.uni WL_%=;\n\t"
            "WD_%=:\n\t}"
            :: "r"(mbar), "r"(parity) : "memory");
    }
}
#define LDTM_X32(r, a) \
    asm volatile("tcgen05.ld.sync.aligned.32x32b.x32.b32 " \
        "{%0,%1,%2,%3,%4,%5,%6,%7,%8,%9,%10,%11,%12,%13,%14,%15," \
        "%16,%17,%18,%19,%20,%21,%22,%23,%24,%25,%26,%27,%28,%29,%30,%31}, [%32];" \
        : "=r"((r)[0]),"=r"((r)[1]),"=r"((r)[2]),"=r"((r)[3]),"=r"((r)[4]),"=r"((r)[5]),"=r"((r)[6]),"=r"((r)[7]), \
          "=r"((r)[8]),"=r"((r)[9]),"=r"((r)[10]),"=r"((r)[11]),"=r"((r)[12]),"=r"((r)[13]),"=r"((r)[14]),"=r"((r)[15]), \
          "=r"((r)[16]),"=r"((r)[17]),"=r"((r)[18]),"=r"((r)[19]),"=r"((r)[20]),"=r"((r)[21]),"=r"((r)[22]),"=r"((r)[23]), \
          "=r"((r)[24]),"=r"((r)[25]),"=r"((r)[26]),"=r"((r)[27]),"=r"((r)[28]),"=r"((r)[29]),"=r"((r)[30]),"=r"((r)[31]) \
        : "r"(a))
#endif // HAS_TC

__global__ __launch_bounds__(NTHREADS, 1)
void hyper_tc(const float* __restrict__ x, const float* __restrict__ W,
              const float* __restrict__ bv, float* __restrict__ out)
{
#if HAS_TC
    extern __shared__ char smem[];
    const uint32_t sb  = smem_u32(smem);
    const int tid = threadIdx.x;
    const int wid = tid >> 5;
    const int lid = tid & 31;
    const int nt  = blockIdx.x;              // 0..1 : n-tile
    const int s   = blockIdx.y;              // 0..73: K-split
    const int n0  = nt * 256;
    const int c0  = s * CHPER;
    const int c1  = min(CHUNKS, c0 + CHPER);
    const int nCh = c1 - c0;

    if (wid == 0) TMEM_ALLOC(sb, 512);
    if (tid == 0) {
        #pragma unroll
        for (int st = 0; st < NST; st++) {
            MBAR_INIT(sb + SM_FULL(st), 16);
            MBAR_INIT(sb + SM_EMPTY(st), 1);
        }
    }
    __syncthreads();
    uint32_t tb;
    asm volatile("ld.shared.b32 %0, [%1];" : "=r"(tb) : "r"(sb));

    if (wid == 0) {
        // ================= MMA warp =================
        for (int j = 0; j < nCh; j++) {
            const int st = j % NST;
            mbar_wait(sb + SM_FULL(st), (uint32_t)((j / NST) & 1));
            TC_FENCE_AFTER();
            if (elect1()) {
                uint64_t ad0 = mkdesc(sb + SM_A(st, 0));
                uint64_t ad1 = mkdesc(sb + SM_A(st, 1));
                uint64_t bd  = mkdesc(sb + SM_B(st));
                #pragma unroll
                for (int ks = 0; ks < 4; ks++) {
                    uint32_t en = (j == 0 && ks == 0) ? 0u : 1u;
                    mma_tf32(tb,        ad0 + ks * 2, bd + ks * 2, en);
                    mma_tf32(tb + 256u, ad1 + ks * 2, bd + ks * 2, en);
                }
                TC_COMMIT(sb + SM_EMPTY(st));
            }
        }
    } else {
        // ===== stagers: u in [0,512) =====
        // A role: row r = u&255, kk-half h = u>>8 (kk in [h*16, h*16+16))
        // B role: n-quad nq = u&63 (n = nq*4..+3), kk-group kkg = u>>6 (kk = kkg*4..+3)
        const int u = tid - 32;
        const int r = u & 255;
        const int h = u >> 8;
        const int kh = h * 16;
        const int nq4  = (u & 63) << 2;
        const int kkg4 = (u >> 6) << 2;
        const float* xg = x + (long)r * XCOLS;
        const uint32_t mt  = (uint32_t)(r >> 7);
        const uint32_t m   = (uint32_t)(r & 127);
        const uint32_t arow = m * 128u + (uint32_t)h * 64u;

        float fa[16];
        int   akey_cur = -2;

        // double-buffered, fully converted tf32 payloads (all ALU in prefetch)
        uint32_t avA[16], avB[16];   // A half-row values
        uint32_t bvA[16], bvB[16];   // B 4n x 4kk block (row-major by n)

        auto prefetch = [&](int c, uint32_t (&av)[16], uint32_t (&bq)[16]){
            // ---- B gather: 4 x LDG.128 along n, register-transpose, cvt ----
            float bf[16];
            if (c < 2048) {
                int i0 = (c >> 7) << 5;
                int k  = c & 127;
                const float* base = W + (long)k * WCOLS + (long)(i0 + kkg4) * OUTF + n0 + nq4;
                #pragma unroll
                for (int t = 0; t < 4; t++)
                    *reinterpret_cast<float4*>(&bf[t*4]) =
                        *reinterpret_cast<const float4*>(base + (long)t * OUTF);
            } else if (c < 2064) {
                int i0 = (c - 2048) << 5;
                const float* base = bv + (long)(i0 + kkg4) * OUTF + n0 + nq4;
                #pragma unroll
                for (int t = 0; t < 4; t++)
                    *reinterpret_cast<float4*>(&bf[t*4]) =
                        *reinterpret_cast<const float4*>(base + (long)t * OUTF);
            } else if (c < 2068) {
                int k0 = (c - 2064) << 5;
                const float* base = W + (long)(k0 + kkg4) * WCOLS + WB_OFF + n0 + nq4;
                #pragma unroll
                for (int t = 0; t < 4; t++)
                    *reinterpret_cast<float4*>(&bf[t*4]) =
                        *reinterpret_cast<const float4*>(base + (long)t * WCOLS);
            } else {
                float4 b = *reinterpret_cast<const float4*>(bv + WB_OFF + n0 + nq4);
                #pragma unroll
                for (int t = 0; t < 4; t++)
                    *reinterpret_cast<float4*>(&bf[t*4]) = b;
            }
            // transpose 4kk x 4n -> rows by n: bq[jj*4+t] = bf[t*4+jj]
            #pragma unroll
            for (int jj = 0; jj < 4; jj++)
                #pragma unroll
                for (int t = 0; t < 4; t++)
                    bq[jj*4+t] = f2tf32(bf[t*4+jj]);

            // ---- A values: nv * feats window (cvt'ed) ----
            float nv; int akey;
            if (c < 2048) {
                int i0 = (c >> 7) << 5;
                nv = xg[c & 127]; akey = NOISE + i0;
            } else if (c < 2064) {
                nv = 1.f; akey = NOISE + ((c - 2048) << 5);
            } else if (c < 2068) {
                nv = 1.f; akey = (c - 2064) << 5;
            } else {
                nv = 0.f; akey = -1;
            }
            if (akey >= 0 && akey != akey_cur) {
                #pragma unroll
                for (int q = 0; q < 4; q++) {
                    float4 f = *reinterpret_cast<const float4*>(xg + akey + kh + q * 4);
                    fa[q*4+0] = f.x; fa[q*4+1] = f.y; fa[q*4+2] = f.z; fa[q*4+3] = f.w;
                }
                akey_cur = akey;
            }
            if (akey < 0) {
                #pragma unroll
                for (int t = 0; t < 16; t++) av[t] = 0u;
                if (h == 0) av[0] = f2tf32(1.f);
            } else {
                #pragma unroll
                for (int t = 0; t < 16; t++) av[t] = f2tf32(nv * fa[t]);
            }
        };

        auto stage = [&](int j, const uint32_t (&av)[16], const uint32_t (&bq)[16]){
            const int st = j % NST;
            if (j >= NST) mbar_wait(sb + SM_EMPTY(st), (uint32_t)(((j / NST) - 1) & 1));
            // B block: 4 STS.128 (rows n = nq4+jj, cols kk = kkg4..+3)
            {
                uint32_t bb = sb + SM_B(st);
                #pragma unroll
                for (int jj = 0; jj < 4; jj++) {
                    uint32_t off = (uint32_t)(nq4 + jj) * 128u + (uint32_t)kkg4 * 4u;
                    sts128(bb + sw128(off), bq[jj*4+0], bq[jj*4+1], bq[jj*4+2], bq[jj*4+3]);
                }
            }
            // A half-row: 4 STS.128
            {
                uint32_t ab = sb + SM_A(st, mt);
                #pragma unroll
                for (int q = 0; q < 4; q++) {
                    uint32_t off = arow + (uint32_t)q * 16u;
                    sts128(ab + sw128(off), av[q*4+0], av[q*4+1], av[q*4+2], av[q*4+3]);
                }
            }
            TC_FENCE_BEFORE();
            __syncwarp();
            if (elect1()) MBAR_ARRIVE(sb + SM_FULL(st));
        };

        prefetch(c0, avA, bvA);
        for (int j = 0; j < nCh; j += 2) {
            if (j + 1 < nCh) prefetch(c0 + j + 1, avB, bvB);
            stage(j, avA, bvA);
            if (j + 1 < nCh) {
                if (j + 2 < nCh) prefetch(c0 + j + 2, avA, bvA);
                stage(j + 1, avB, bvB);
            }
        }
    }

    // ---- wait for final MMA completion ----
    const int jl = nCh - 1;
    mbar_wait(sb + SM_EMPTY(jl % NST), (uint32_t)((jl / NST) & 1));
    TC_FENCE_AFTER();
    __syncthreads();

    // ---- epilogue: warps 0-7 read TMEM, write split partials ----
    if (wid < 8) {
        const int sub = wid & 3;
        const int grp = wid >> 2;
        const int mg  = grp * 128 + sub * 32 + lid;
        float* dst = g_scratch + ((long)s * 256 + mg) * 512 + n0;
        #pragma unroll
        for (int c = 0; c < 8; c++) {
            uint32_t rr[32];
            LDTM_X32(rr, tb + (uint32_t)grp * 256u + (uint32_t)c * 32u);
            TC_WAIT_LD();
            #pragma unroll
            for (int q = 0; q < 8; q++) {
                *reinterpret_cast<float4*>(dst + c * 32 + q * 4) =
                    make_float4(__uint_as_float(rr[q*4+0]), __uint_as_float(rr[q*4+1]),
                                __uint_as_float(rr[q*4+2]), __uint_as_float(rr[q*4+3]));
            }
        }
    }
    if (wid == 0) { TMEM_RELINQ(); TMEM_DEALLOC(tb, 512); }

    // ---- grid-wide sense-reversing barrier (148 CTAs, all resident) ----
    __threadfence();
    __syncthreads();
    if (tid == 0) {
        unsigned sv = g_bar_sense;
        unsigned old = atomicAdd(&g_bar_cnt, 1u);
        if (old == (unsigned)(NCTAS - 1)) {
            g_bar_cnt = 0;
            __threadfence();
            g_bar_sense = sv ^ 1u;
        } else {
            while (g_bar_sense == sv) { }
        }
    }
    __syncthreads();

    // ---- fused split reduction: 65536 float2 outputs ----
    {
        const int cta = blockIdx.y * 2 + blockIdx.x;
        const float2* sc = reinterpret_cast<const float2*>(g_scratch);
        for (int e = cta * NTHREADS + tid; e < ELEMS2; e += NT_TOTAL) {
            float2 a0 = make_float2(0.f, 0.f), a1 = a0, a2 = a0, a3 = a0;
            #pragma unroll
            for (int t = 0; t < 18; t++) {
                float2 u0 = sc[(size_t)(t)      * ELEMS2 + e];
                float2 u1 = sc[(size_t)(t + 18) * ELEMS2 + e];
                float2 u2 = sc[(size_t)(t + 36) * ELEMS2 + e];
                float2 u3 = sc[(size_t)(t + 54) * ELEMS2 + e];
                a0.x += u0.x; a0.y += u0.y;
                a1.x += u1.x; a1.y += u1.y;
                a2.x += u2.x; a2.y += u2.y;
                a3.x += u3.x; a3.y += u3.y;
            }
            {
                float2 u = sc[(size_t)72 * ELEMS2 + e];
                float2 v = sc[(size_t)73 * ELEMS2 + e];
                a0.x += u.x; a0.y += u.y;
                a1.x += v.x; a1.y += v.y;
            }
            reinterpret_cast<float2*>(out)[e] =
                make_float2(a0.x + a1.x + a2.x + a3.x, a0.y + a1.y + a2.y + a3.y);
        }
    }
#endif // HAS_TC
}

extern "C" void kernel_launch(void* const* d_in, const int* in_sizes, int n_in,
                              void* d_out, int out_size)
{
    const float* x  = (const float*)d_in[0];   // (256, 640)
    const float* W  = (const float*)d_in[1];   // (128, 262656)
    const float* bv = (const float*)d_in[2];   // (262656,)
    float* out = (float*)d_out;                // (256, 512)

    cudaFuncSetAttribute(hyper_tc, cudaFuncAttributeMaxDynamicSharedMemorySize, SMEM_TOTAL);
    hyper_tc<<<dim3(2, SPLITS), NTHREADS, SMEM_TOTAL>>>(x, W, bv, out);
}

// round 17
// speedup vs baseline: 1.3634x; 1.3634x over previous
#include <cuda_runtime.h>
#include <cstdint>

// ---------------- arch-feature detection (proven working) ----------------
#if defined(__CUDA_ARCH__) && (defined(__CUDA_ARCH_FEAT_SM103_ALL) || defined(__CUDA_ARCH_FEAT_SM100_ALL) || defined(__CUDA_ARCH_SPECIFIC__))
#define HAS_TC 1
#else
#define HAS_TC 0
#endif

#define NOISE   128
#define OUTF    512
#define XCOLS   640
#define WCOLS   262656
#define WB_OFF  262144

// chunk space: 2048 main (i0-outer, k-inner) + 16 feat-bias + 4 noise-bias + 1 const
#define CHUNKS  2069
#define SPLITS  74
#define CHPER   28
#define NST     3
#define NTHREADS 288       // warp 0 = MMA warp, warps 1-8 = 256 stagers

#define SM_A(st, mt) (1024u + ((st)*2u + (mt))*16384u)    // 6 x 16KB A tiles
#define SM_B(st)     (99328u + (st)*32768u)               // 3 x 32KB B tiles
#define SMEM_TOTAL   197632
#define SM_FULL(st)  (8u  + (st)*8u)
#define SM_EMPTY(st) (40u + (st)*8u)

// idesc: dtype F32(1)@[4], a/b TF32(2)@[7:9]/[10:12], N=256 -> 32@[17:22], M=128 -> 8@[24:28]
#define IDESC_TF32 ((1u<<4)|(2u<<7)|(2u<<10)|(32u<<17)|(8u<<24))

__device__ float g_scratch[(size_t)SPLITS * 256 * 512];   // split partials (38.8MB)

#if HAS_TC
// ---------------- PTX helpers ----------------
__device__ __forceinline__ uint32_t smem_u32(const void* p){
    uint32_t a;
    asm("{ .reg .u64 t; cvta.to.shared.u64 t, %1; cvt.u32.u64 %0, t; }" : "=r"(a) : "l"(p));
    return a;
}
__device__ __forceinline__ uint32_t sw128(uint32_t o){ return o ^ ((o >> 3) & 0x70u); }
__device__ __forceinline__ uint32_t f2tf32(float f){
    uint32_t r; asm("cvt.rna.tf32.f32 %0, %1;" : "=r"(r) : "f"(f)); return r;
}
__device__ __forceinline__ void sts128(uint32_t addr, uint32_t a, uint32_t b, uint32_t c, uint32_t d){
    asm volatile("st.shared.v4.b32 [%0], {%1,%2,%3,%4};"
                 :: "r"(addr), "r"(a), "r"(b), "r"(c), "r"(d) : "memory");
}
__device__ __forceinline__ bool elect1(){
    uint32_t p;
    asm volatile("{\n\t.reg .pred P;\n\telect.sync _|P, 0xFFFFFFFF;\n\tselp.b32 %0, 1, 0, P;\n\t}" : "=r"(p));
    return p != 0;
}
static constexpr unsigned long long DESC_BASE_SW128 =
    (2ull << 61) | (1ull << 46) | (64ull << 32) | (1ull << 16);
__device__ __forceinline__ uint64_t mkdesc(uint32_t addr){
    return DESC_BASE_SW128 | (uint64_t)((addr >> 4) & 0x3FFFu);
}
__device__ __forceinline__ void mma_tf32(uint32_t d, uint64_t ad, uint64_t bd, uint32_t en){
    asm volatile(
        "{\n\t.reg .pred p;\n\tsetp.ne.u32 p, %4, 0;\n\t"
        "tcgen05.mma.cta_group::1.kind::tf32 [%0], %1, %2, %3, {%5,%5,%5,%5}, p;\n\t}"
        :: "r"(d), "l"(ad), "l"(bd), "r"(IDESC_TF32), "r"(en), "r"(0u) : "memory");
}
#define TMEM_ALLOC(smem_addr, ncols) \
    asm volatile("tcgen05.alloc.cta_group::1.sync.aligned.shared::cta.b32 [%0], %1;" \
                 :: "r"(smem_addr), "r"((uint32_t)(ncols)) : "memory")
#define TMEM_DEALLOC(tmem, ncols) \
    asm volatile("tcgen05.dealloc.cta_group::1.sync.aligned.b32 %0, %1;" :: "r"(tmem), "r"((uint32_t)(ncols)))
#define TMEM_RELINQ() asm volatile("tcgen05.relinquish_alloc_permit.cta_group::1.sync.aligned;")
#define MBAR_INIT(a, n) \
    asm volatile("mbarrier.init.shared.b64 [%0], %1;" :: "r"(a), "r"((uint32_t)(n)) : "memory")
#define MBAR_ARRIVE(a) \
    asm volatile("mbarrier.arrive.shared.b64 _, [%0];" :: "r"(a) : "memory")
#define TC_COMMIT(a) \
    asm volatile("tcgen05.commit.cta_group::1.mbarrier::arrive::one.shared::cluster.b64 [%0];" :: "r"(a) : "memory")
#define FENCE_ASYNC() asm volatile("fence.proxy.async.shared::cta;" ::: "memory")
#define TC_FENCE_AFTER() asm volatile("tcgen05.fence::after_thread_sync;" ::: "memory")
#define TC_WAIT_LD() asm volatile("tcgen05.wait::ld.sync.aligned;" ::: "memory")

__device__ __forceinline__ void mbar_wait(uint32_t mbar, uint32_t parity){
    uint32_t done;
    asm volatile(
        "{\n\t.reg .pred p;\n\t"
        "mbarrier.try_wait.parity.acquire.cta.shared::cta.b64 p, [%1], %2;\n\t"
        "selp.b32 %0, 1, 0, p;\n\t}"
        : "=r"(done) : "r"(mbar), "r"(parity) : "memory");
    if (!done) {
        asm volatile(
            "{\n\t.reg .pred P1;\n\t"
            "WL_%=:\n\t"
            "mbarrier.try_wait.parity.acquire.cta.shared::cta.b64 P1, [%0], %1, 0x989680;\n\t"
            "@P1 bra.uni WD_%=;\n\t"
            "bra.uni WL_%=;\n\t"
            "WD_%=:\n\t}"
            :: "r"(mbar), "r"(parity) : "memory");
    }
}
#define LDTM_X32(r, a) \
    asm volatile("tcgen05.ld.sync.aligned.32x32b.x32.b32 " \
        "{%0,%1,%2,%3,%4,%5,%6,%7,%8,%9,%10,%11,%12,%13,%14,%15," \
        "%16,%17,%18,%19,%20,%21,%22,%23,%24,%25,%26,%27,%28,%29,%30,%31}, [%32];" \
        : "=r"((r)[0]),"=r"((r)[1]),"=r"((r)[2]),"=r"((r)[3]),"=r"((r)[4]),"=r"((r)[5]),"=r"((r)[6]),"=r"((r)[7]), \
          "=r"((r)[8]),"=r"((r)[9]),"=r"((r)[10]),"=r"((r)[11]),"=r"((r)[12]),"=r"((r)[13]),"=r"((r)[14]),"=r"((r)[15]), \
          "=r"((r)[16]),"=r"((r)[17]),"=r"((r)[18]),"=r"((r)[19]),"=r"((r)[20]),"=r"((r)[21]),"=r"((r)[22]),"=r"((r)[23]), \
          "=r"((r)[24]),"=r"((r)[25]),"=r"((r)[26]),"=r"((r)[27]),"=r"((r)[28]),"=r"((r)[29]),"=r"((r)[30]),"=r"((r)[31]) \
        : "r"(a))
#endif // HAS_TC

__global__ __launch_bounds__(NTHREADS, 1)
void hyper_tc(const float* __restrict__ x, const float* __restrict__ W,
              const float* __restrict__ bv)
{
#if HAS_TC
    extern __shared__ char smem[];
    const uint32_t sb  = smem_u32(smem);
    const int tid = threadIdx.x;
    const int wid = tid >> 5;
    const int lid = tid & 31;
    const int nt  = blockIdx.x;              // 0..1 : n-tile
    const int s   = blockIdx.y;              // 0..73: K-split
    const int n0  = nt * 256;
    const int c0  = s * CHPER;
    const int c1  = min(CHUNKS, c0 + CHPER);
    const int nCh = c1 - c0;

    if (wid == 0) TMEM_ALLOC(sb, 512);
    if (tid == 0) {
        #pragma unroll
        for (int st = 0; st < NST; st++) {
            MBAR_INIT(sb + SM_FULL(st), 256);   // 256 stager arrivals
            MBAR_INIT(sb + SM_EMPTY(st), 1);    // tcgen05.commit
        }
    }
    __syncthreads();
    uint32_t tb;
    asm volatile("ld.shared.b32 %0, [%1];" : "=r"(tb) : "r"(sb));

    if (wid == 0) {
        // ================= MMA warp =================
        for (int j = 0; j < nCh; j++) {
            const int st = j % NST;
            mbar_wait(sb + SM_FULL(st), (uint32_t)((j / NST) & 1));
            if (elect1()) {
                uint64_t ad0 = mkdesc(sb + SM_A(st, 0));
                uint64_t ad1 = mkdesc(sb + SM_A(st, 1));
                uint64_t bd  = mkdesc(sb + SM_B(st));
                #pragma unroll
                for (int ks = 0; ks < 4; ks++) {
                    uint32_t en = (j == 0 && ks == 0) ? 0u : 1u;
                    mma_tf32(tb,        ad0 + ks * 2, bd + ks * 2, en);
                    mma_tf32(tb + 256u, ad1 + ks * 2, bd + ks * 2, en);
                }
                TC_COMMIT(sb + SM_EMPTY(st));
            }
        }
    } else {
        // ================= stager threads: u in [0,256) =================
        const int u = tid - 32;
        const float* xg = x + (long)u * XCOLS;
        const uint32_t mt  = (uint32_t)(u >> 7);
        const uint32_t m   = (uint32_t)(u & 127);
        const uint32_t arow = m * 128u;
        const uint32_t brow = (uint32_t)u * 128u;

        float fa[32];
        int   akey_cur = -2;

        for (int j = 0; j < nCh; j++) {
            const int c  = c0 + j;
            const int st = j % NST;

            // ---- decode chunk ----
            const float* bp; long bstr; float nv; int akey; int case3 = 0;
            if (c < 2048) {                      // main: i0-outer, k-inner
                int i0 = (c >> 7) << 5;
                int k  = c & 127;
                bp = W + (long)k * WCOLS + (long)i0 * OUTF + n0 + u; bstr = OUTF;
                nv = xg[k];
                akey = NOISE + i0;
            } else if (c < 2064) {               // feats @ bias-weight
                int i0 = (c - 2048) << 5;
                bp = bv + (long)i0 * OUTF + n0 + u; bstr = OUTF;
                nv = 1.f;
                akey = NOISE + i0;
            } else if (c < 2068) {               // noise @ W-bias
                int k0 = (c - 2064) << 5;
                bp = W + (long)k0 * WCOLS + WB_OFF + n0 + u; bstr = WCOLS;
                nv = 1.f;
                akey = k0;
            } else {                             // const bias
                bp = bv + WB_OFF + n0 + u; bstr = 0;
                nv = 0.f; akey = -1; case3 = 1;
            }

            // ---- issue LDGs before the empty-wait (overlap wait with memory) ----
            if (akey >= 0 && akey != akey_cur) {
                #pragma unroll
                for (int q = 0; q < 8; q++) {
                    float4 f = *reinterpret_cast<const float4*>(xg + akey + q * 4);
                    fa[q*4+0] = f.x; fa[q*4+1] = f.y; fa[q*4+2] = f.z; fa[q*4+3] = f.w;
                }
                akey_cur = akey;
            }
            float br[32];
            #pragma unroll
            for (int kk = 0; kk < 32; kk++) br[kk] = bp[(long)kk * bstr];

            // ---- wait for stage buffers free ----
            if (j >= NST) mbar_wait(sb + SM_EMPTY(st), (uint32_t)(((j / NST) - 1) & 1));

            // ---- stage B row (8 STS.128) ----
            {
                uint32_t bb = sb + SM_B(st);
                #pragma unroll
                for (int q = 0; q < 8; q++) {
                    uint32_t off = brow + (uint32_t)q * 16u;
                    sts128(bb + sw128(off),
                           f2tf32(br[q*4+0]), f2tf32(br[q*4+1]),
                           f2tf32(br[q*4+2]), f2tf32(br[q*4+3]));
                }
            }
            // ---- stage A row (8 STS.128) ----
            {
                uint32_t ab = sb + SM_A(st, mt);
                #pragma unroll
                for (int q = 0; q < 8; q++) {
                    float v0, v1, v2, v3;
                    if (case3) {
                        v0 = (q == 0) ? 1.f : 0.f; v1 = 0.f; v2 = 0.f; v3 = 0.f;
                    } else {
                        v0 = nv * fa[q*4+0]; v1 = nv * fa[q*4+1];
                        v2 = nv * fa[q*4+2]; v3 = nv * fa[q*4+3];
                    }
                    uint32_t off = arow + (uint32_t)q * 16u;
                    sts128(ab + sw128(off), f2tf32(v0), f2tf32(v1), f2tf32(v2), f2tf32(v3));
                }
            }
            FENCE_ASYNC();
            MBAR_ARRIVE(sb + SM_FULL(st));
        }
    }

    // ---- all threads wait for final MMA completion ----
    const int jl = nCh - 1;
    mbar_wait(sb + SM_EMPTY(jl % NST), (uint32_t)((jl / NST) & 1));
    TC_FENCE_AFTER();
    __syncthreads();

    // ---- epilogue: warps 0-7 read TMEM, write split partials ----
    if (wid < 8) {
        const int sub = wid & 3;
        const int grp = wid >> 2;                 // m-tile
        const int mg  = grp * 128 + sub * 32 + lid;
        float* dst = g_scratch + ((long)s * 256 + mg) * 512 + n0;
        #pragma unroll
        for (int c = 0; c < 8; c++) {
            uint32_t r[32];
            LDTM_X32(r, tb + (uint32_t)grp * 256u + (uint32_t)c * 32u);
            TC_WAIT_LD();
            #pragma unroll
            for (int q = 0; q < 8; q++) {
                *reinterpret_cast<float4*>(dst + c * 32 + q * 4) =
                    make_float4(__uint_as_float(r[q*4+0]), __uint_as_float(r[q*4+1]),
                                __uint_as_float(r[q*4+2]), __uint_as_float(r[q*4+3]));
            }
        }
    }

    __syncthreads();
    if (wid == 0) { TMEM_RELINQ(); TMEM_DEALLOC(tb, 512); }
#endif // HAS_TC
}

// ------- split reduction: 65536 float2 outputs, 512 blocks, 4 load streams -------
__global__ void reduce_k(float* __restrict__ out)
{
    const int g = blockIdx.x * blockDim.x + threadIdx.x;     // 0..65535 (float2 index)
    const float2* sc = reinterpret_cast<const float2*>(g_scratch);
    float2 a0 = make_float2(0.f, 0.f), a1 = a0, a2 = a0, a3 = a0;
    #pragma unroll
    for (int t = 0; t < 18; t++) {
        float2 u0 = sc[(size_t)(t)      * 65536 + g];
        float2 u1 = sc[(size_t)(t + 18) * 65536 + g];
        float2 u2 = sc[(size_t)(t + 36) * 65536 + g];
        float2 u3 = sc[(size_t)(t + 54) * 65536 + g];
        a0.x += u0.x; a0.y += u0.y;
        a1.x += u1.x; a1.y += u1.y;
        a2.x += u2.x; a2.y += u2.y;
        a3.x += u3.x; a3.y += u3.y;
    }
    {   // tail: splits 72, 73
        float2 u = sc[(size_t)72 * 65536 + g];
        float2 v = sc[(size_t)73 * 65536 + g];
        a0.x += u.x; a0.y += u.y;
        a1.x += v.x; a1.y += v.y;
    }
    reinterpret_cast<float2*>(out)[g] =
        make_float2(a0.x + a1.x + a2.x + a3.x, a0.y + a1.y + a2.y + a3.y);
}

extern "C" void kernel_launch(void* const* d_in, const int* in_sizes, int n_in,
                              void* d_out, int out_size)
{
    const float* x  = (const float*)d_in[0];   // (256, 640)
    const float* W  = (const float*)d_in[1];   // (128, 262656)
    const float* bv = (const float*)d_in[2];   // (262656,)
    float* out = (float*)d_out;                // (256, 512)

    cudaFuncSetAttribute(hyper_tc, cudaFuncAttributeMaxDynamicSharedMemorySize, SMEM_TOTAL);
    hyper_tc<<<dim3(2, SPLITS), NTHREADS, SMEM_TOTAL>>>(x, W, bv);
    reduce_k<<<512, 128>>>(out);
}